// round 5
// baseline (speedup 1.0000x reference)
#include <cuda_runtime.h>
#include <cstdint>

// out[e, 0:128]   = node_states[src[e], :]
// out[e, 128:256] = node_states[tgt[e], :]
// One warp per TWO edges (best config, R3: 49.6us). This round: __stwt
// (write-through) instead of __stcs — output is never re-read, so skip L2
// allocation entirely and leave the L2 array to the node_states gather set.
// Binder hypothesis test: LTS-array-bound -> ~47us; DRAM-write-bound -> neutral.

__global__ __launch_bounds__(256) void node_propagate_kernel(
    const float4* __restrict__ ns,   // [N_NODES, 32] as float4
    const int* __restrict__ src,     // [E] int32
    const int* __restrict__ tgt,     // [E] int32
    float4* __restrict__ out,        // [E, 64] as float4
    int E)
{
    const int gwarp = (int)((blockIdx.x * (unsigned)blockDim.x + threadIdx.x) >> 5);
    const int lane  = threadIdx.x & 31;
    const int e0    = gwarp * 2;
    if (e0 >= E) return;
    const bool two = (e0 + 1 < E);

    // Index pairs: adjacent int32s -> one 8B broadcast load each.
    int2 s2, t2;
    if (two) {
        s2 = *(const int2*)(src + e0);
        t2 = *(const int2*)(tgt + e0);
    } else {
        s2 = make_int2(__ldg(&src[e0]), 0);
        t2 = make_int2(__ldg(&tgt[e0]), 0);
    }

    // 4 independent gathers in flight (node_states is 5.12 MB, L2-resident).
    const float4 a0 = __ldg(&ns[(size_t)s2.x * 32 + lane]);
    const float4 b0 = __ldg(&ns[(size_t)t2.x * 32 + lane]);
    float4 a1, b1;
    if (two) {
        a1 = __ldg(&ns[(size_t)s2.y * 32 + lane]);
        b1 = __ldg(&ns[(size_t)t2.y * 32 + lane]);
    }

    // Write-through stores: no L2 allocation for the 328 MB output stream.
    float4* o = out + (size_t)e0 * 64;
    __stwt(o + lane,      a0);
    __stwt(o + 32 + lane, b0);
    if (two) {
        __stwt(o + 64 + lane, a1);
        __stwt(o + 96 + lane, b1);
    }
}

extern "C" void kernel_launch(void* const* d_in, const int* in_sizes, int n_in,
                              void* d_out, int out_size)
{
    const float4* ns  = (const float4*)d_in[0];
    const int*    src = (const int*)d_in[1];
    const int*    tgt = (const int*)d_in[2];
    float4*       out = (float4*)d_out;

    const int E = in_sizes[1];  // 320000 edges

    const int threads = 256;                    // 8 warps -> 16 edges per block
    const int warps   = (E + 1) / 2;
    const int blocks  = (warps * 32 + threads - 1) / threads;

    node_propagate_kernel<<<blocks, threads>>>(ns, src, tgt, out, E);
}

// round 6
// speedup vs baseline: 1.0333x; 1.0333x over previous
#include <cuda_runtime.h>
#include <cstdint>

// out[e, 0:128]   = node_states[src[e], :]
// out[e, 128:256] = node_states[tgt[e], :]
// One warp per TWO edges, branchless fast path (E=320000 is even; odd-E tail
// handled by a tiny second launch). __stcs stores confirmed best (R5: __stwt
// regressed -> DRAM-write-bound, evict-first line evictions win).
// Steady state: 328 MB writes / 49.6us = 6.6 TB/s ~ 83% of HBM spec.

__global__ __launch_bounds__(512) void node_propagate_kernel(
    const float4* __restrict__ ns,   // [N_NODES, 32] as float4
    const int* __restrict__ src,     // [E] int32
    const int* __restrict__ tgt,     // [E] int32
    float4* __restrict__ out,        // [E, 64] as float4
    int nPairs)                      // E/2
{
    const int gwarp = (int)((blockIdx.x * (unsigned)blockDim.x + threadIdx.x) >> 5);
    const int lane  = threadIdx.x & 31;
    if (gwarp >= nPairs) return;
    const int e0 = gwarp * 2;

    // Index pairs: adjacent int32s -> one 8B broadcast load each.
    const int2 s2 = *(const int2*)(src + e0);
    const int2 t2 = *(const int2*)(tgt + e0);

    // 4 independent gathers in flight (node_states is 5.12 MB, L2-resident).
    const float4 a0 = __ldg(&ns[(size_t)s2.x * 32 + lane]);
    const float4 b0 = __ldg(&ns[(size_t)t2.x * 32 + lane]);
    const float4 a1 = __ldg(&ns[(size_t)s2.y * 32 + lane]);
    const float4 b1 = __ldg(&ns[(size_t)t2.y * 32 + lane]);

    // Evict-first stores: full-line eviction to DRAM, protect L2 gather set.
    float4* o = out + (size_t)e0 * 64;
    __stcs(o +      lane, a0);
    __stcs(o + 32 + lane, b0);
    __stcs(o + 64 + lane, a1);
    __stcs(o + 96 + lane, b1);
}

// Tail kernel for odd E (not used when E is even).
__global__ void node_propagate_tail(
    const float4* __restrict__ ns,
    const int* __restrict__ src,
    const int* __restrict__ tgt,
    float4* __restrict__ out,
    int e)
{
    const int lane = threadIdx.x & 31;
    const int s = __ldg(&src[e]);
    const int t = __ldg(&tgt[e]);
    const float4 a = __ldg(&ns[(size_t)s * 32 + lane]);
    const float4 b = __ldg(&ns[(size_t)t * 32 + lane]);
    float4* o = out + (size_t)e * 64;
    __stcs(o + lane,      a);
    __stcs(o + 32 + lane, b);
}

extern "C" void kernel_launch(void* const* d_in, const int* in_sizes, int n_in,
                              void* d_out, int out_size)
{
    const float4* ns  = (const float4*)d_in[0];
    const int*    src = (const int*)d_in[1];
    const int*    tgt = (const int*)d_in[2];
    float4*       out = (float4*)d_out;

    const int E      = in_sizes[1];   // 320000 edges
    const int nPairs = E / 2;

    const int threads = 512;          // 16 warps -> 32 edges per block
    const int blocks  = (nPairs * 32 + threads - 1) / threads;

    node_propagate_kernel<<<blocks, threads>>>(ns, src, tgt, out, nPairs);

    if (E & 1)  // odd tail (never taken for E=320000)
        node_propagate_tail<<<1, 32>>>(ns, src, tgt, out, E - 1);
}